// round 16
// baseline (speedup 1.0000x reference)
#include <cuda_runtime.h>
#include <cuda_fp16.h>
#include <math.h>
#include <stdint.h>

// ---------------- problem constants ----------------
#define BATCH   32
#define NSEQ    1024
#define DIM     512
#define NHEAD   8
#define DHEAD   64
#define QKV_LD  1536

// ---------------- scratch (device globals) ----------------
__device__ __half g_x16  [(size_t)BATCH * NSEQ * DIM];     // x in fp16
__device__ __half g_qkv16[(size_t)BATCH * NSEQ * QKV_LD];  // qkv fp16
__device__ __half g_ao16 [(size_t)BATCH * NSEQ * DIM];     // attn out fp16
__device__ __half g_wqkvT[(size_t)QKV_LD * DIM];           // [N][K] fp16
__device__ __half g_woutT[(size_t)DIM * DIM];              // [N][K] fp16

// =====================================================================
// helpers
// =====================================================================
__device__ __forceinline__ uint32_t smem_u32(const void* p) {
    uint32_t a;
    asm("{ .reg .u64 t; cvta.to.shared.u64 t, %1; cvt.u32.u64 %0, t; }"
        : "=r"(a) : "l"(p));
    return a;
}

__device__ __forceinline__ uint32_t pack2h(float a, float b) {
    __half2 h = __floats2half2_rn(a, b);
    return *reinterpret_cast<uint32_t*>(&h);
}

// MUFU exp2 — 1 issue slot, ~2^-22 rel accuracy
__device__ __forceinline__ float ex2a(float x) {
    float r;
    asm("ex2.approx.f32 %0, %1;" : "=f"(r) : "f"(x));
    return r;
}

__device__ __forceinline__ void mma_f16(float* c, const uint32_t* a,
                                        const uint32_t* b) {
    asm volatile(
        "mma.sync.aligned.m16n8k16.row.col.f32.f16.f16.f32 "
        "{%0,%1,%2,%3}, {%4,%5,%6,%7}, {%8,%9}, {%0,%1,%2,%3};\n"
        : "+f"(c[0]), "+f"(c[1]), "+f"(c[2]), "+f"(c[3])
        : "r"(a[0]), "r"(a[1]), "r"(a[2]), "r"(a[3]),
          "r"(b[0]), "r"(b[1]));
}

#define LDSM_X4(r0, r1, r2, r3, addr)                                        \
    asm volatile("ldmatrix.sync.aligned.m8n8.x4.shared.b16 {%0,%1,%2,%3}, [%4];" \
        : "=r"(r0), "=r"(r1), "=r"(r2), "=r"(r3) : "r"(addr))

#define LDSM_X4_T(r0, r1, r2, r3, addr)                                      \
    asm volatile("ldmatrix.sync.aligned.m8n8.x4.trans.shared.b16 {%0,%1,%2,%3}, [%4];" \
        : "=r"(r0), "=r"(r1), "=r"(r2), "=r"(r3) : "r"(addr))

__device__ __forceinline__ void cp16(uint32_t dst, const void* src) {
    asm volatile("cp.async.cg.shared.global [%0], [%1], 16;"
                 :: "r"(dst), "l"(src));
}
#define CP_COMMIT() asm volatile("cp.async.commit_group;" ::: "memory")
#define CP_WAIT2()  asm volatile("cp.async.wait_group 2;" ::: "memory")
#define CP_WAIT1()  asm volatile("cp.async.wait_group 1;" ::: "memory")
#define CP_WAIT0()  asm volatile("cp.async.wait_group 0;" ::: "memory")

// 16B-chunk swizzle within 128B rows
#define SWZ128(r, c) (((c) * 16) ^ (((r) & 7) * 16))

// =====================================================================
// converters
// =====================================================================
__global__ __launch_bounds__(256) void f32to16(
    const float* __restrict__ in, __half* __restrict__ out, int n4)
{
    int i = blockIdx.x * blockDim.x + threadIdx.x;
    if (i < n4) {
        float4 v = reinterpret_cast<const float4*>(in)[i];
        uint2 u = {pack2h(v.x, v.y), pack2h(v.z, v.w)};
        reinterpret_cast<uint2*>(out)[i] = u;
    }
}

// out[n*K + k] = (half)in[k*N + n]
__global__ __launch_bounds__(256) void transpose16(
    const float* __restrict__ in, __half* __restrict__ out, int K, int N)
{
    __shared__ float t[32][33];
    int k0 = blockIdx.y * 32, n0 = blockIdx.x * 32;
    int x = threadIdx.x, y = threadIdx.y;        // 32 x 8
    #pragma unroll
    for (int i = 0; i < 32; i += 8)
        t[y + i][x] = in[(size_t)(k0 + y + i) * N + n0 + x];
    __syncthreads();
    #pragma unroll
    for (int i = 0; i < 32; i += 8)
        out[(size_t)(n0 + y + i) * K + k0 + x] = __float2half(t[x][y + i]);
}

// =====================================================================
// fp16 GEMM, cp.async 3-stage (unchanged — stable ~146us)
// =====================================================================
#define HG_STAGE 32768                         // A 16KB + B 16KB
#define HG_SMEM  (3 * HG_STAGE)

template <bool OUT_HALF>
__global__ __launch_bounds__(256, 2) void hgemm(
    const __half* __restrict__ A, const __half* __restrict__ Bt,
    void* __restrict__ Cv, int K, int Nglob, const float* __restrict__ bias)
{
    extern __shared__ __align__(16) char sm[];
    const uint32_t smb = smem_u32(sm);
    const int tid = threadIdx.x, lane = tid & 31, wid = tid >> 5;
    const int g = lane >> 2, t4 = lane & 3;
    const int wm = wid >> 2, wn = wid & 3;
    const int row0 = blockIdx.y * 128, col0 = blockIdx.x * 128;

    auto issue = [&](int st, int kt) {
        const uint32_t dA = smb + st * HG_STAGE;
        const uint32_t dB = dA + 16384;
        #pragma unroll
        for (int i = 0; i < 4; i++) {
            int s = tid + i * 256, r = s >> 3, c = s & 7;
            cp16(dA + r * 128 + SWZ128(r, c),
                 A + (size_t)(row0 + r) * K + kt * 64 + c * 8);
            cp16(dB + r * 128 + SWZ128(r, c),
                 Bt + (size_t)(col0 + r) * K + kt * 64 + c * 8);
        }
        CP_COMMIT();
    };

    float acc[4][4][4];
    #pragma unroll
    for (int mt = 0; mt < 4; mt++)
        #pragma unroll
        for (int nt = 0; nt < 4; nt++)
            #pragma unroll
            for (int i = 0; i < 4; i++) acc[mt][nt][i] = 0.0f;

    const int KT = K / 64;
    issue(0, 0);
    issue(1, 1);

    int st = 0, sti = 2;
    for (int t = 0; t < KT; t++) {
        if (t == KT - 1) { CP_WAIT0(); } else { CP_WAIT1(); }
        __syncthreads();
        if (t + 2 < KT) issue(sti, t + 2);

        const uint32_t sA = smb + st * HG_STAGE;
        const uint32_t sB = sA + 16384;

        #pragma unroll
        for (int ks = 0; ks < 4; ks++) {
            uint32_t af[4][4];
            #pragma unroll
            for (int mt = 0; mt < 4; mt++) {
                int r = wm * 64 + mt * 16 + (lane & 15);
                int c = ks * 2 + (lane >> 4);
                LDSM_X4(af[mt][0], af[mt][1], af[mt][2], af[mt][3],
                        sA + r * 128 + SWZ128(r, c));
            }
            uint32_t bf[4][2];
            #pragma unroll
            for (int np = 0; np < 2; np++) {
                int r = wn * 32 + np * 16 + (lane & 7) + ((lane >> 4) << 3);
                int c = ks * 2 + ((lane >> 3) & 1);
                LDSM_X4(bf[np*2][0], bf[np*2][1], bf[np*2+1][0], bf[np*2+1][1],
                        sB + r * 128 + SWZ128(r, c));
            }
            #pragma unroll
            for (int mt = 0; mt < 4; mt++)
                #pragma unroll
                for (int nt = 0; nt < 4; nt++)
                    mma_f16(acc[mt][nt], af[mt], bf[nt]);
        }

        if (++st == 3) st = 0;
        if (++sti == 3) sti = 0;
    }

    #pragma unroll
    for (int mt = 0; mt < 4; mt++) {
        const int r = row0 + wm * 64 + mt * 16 + g;
        #pragma unroll
        for (int nt = 0; nt < 4; nt++) {
            const int cc = col0 + wn * 32 + nt * 8 + t4 * 2;
            if (OUT_HALF) {
                __half* C = (__half*)Cv;
                *reinterpret_cast<uint32_t*>(&C[(size_t)r * Nglob + cc]) =
                    pack2h(acc[mt][nt][0], acc[mt][nt][1]);
                *reinterpret_cast<uint32_t*>(&C[(size_t)(r + 8) * Nglob + cc]) =
                    pack2h(acc[mt][nt][2], acc[mt][nt][3]);
            } else {
                float* C = (float*)Cv;
                float b0 = bias[cc], b1 = bias[cc + 1];
                *reinterpret_cast<float2*>(&C[(size_t)r * Nglob + cc]) =
                    make_float2(acc[mt][nt][0] + b0, acc[mt][nt][1] + b1);
                *reinterpret_cast<float2*>(&C[(size_t)(r + 8) * Nglob + cc]) =
                    make_float2(acc[mt][nt][2] + b0, acc[mt][nt][3] + b1);
            }
        }
    }
}

// =====================================================================
// flash attention v16 — crossbar-redundancy fix.
// CTA: 128 q-rows, 256 threads. Warp = 32 q-rows x 32 j-cols
// (rowg = wid>>1, jg = wid&1). K/V fragment redundancy 8 -> 4.
// Q fragments fully hoisted (zero steady-state Q crossbar).
// jg pairs hold partial O/l over their j-half; one smem reduce at end.
// smem: Q 16KB | 4 stages x (K 8KB + V 8KB) = 80KB; epilogue reuses KV.
// =====================================================================
#define FL_Q     0
#define FL_KV    16384
#define FL_STAGE 16384
#define FL_SMEM  (16384 + 4 * FL_STAGE)

__global__ __launch_bounds__(256, 2) void hflash(
    const __half* __restrict__ qkv, const float* __restrict__ mask,
    __half* __restrict__ out)
{
    extern __shared__ __align__(16) char sm[];
    const uint32_t smb = smem_u32(sm);
    const int tid = threadIdx.x, lane = tid & 31, wid = tid >> 5;
    const int g = lane >> 2, t4 = lane & 3;
    const int b = blockIdx.z, h = blockIdx.y, i0 = blockIdx.x * 128;
    const int rowg = wid >> 1, jg = wid & 1;
    const int wrow = rowg * 32;                   // warp's q-row base

    auto issue_kv = [&](int st, int jt) {
        const uint32_t dst = smb + FL_KV + st * FL_STAGE;
        #pragma unroll
        for (int i = 0; i < 4; i++) {
            int s = tid + i * 256;
            int half_v = (s >= 512);
            int r = (s & 511) >> 3, c = s & 7;
            const __half* src = qkv + ((size_t)(b * NSEQ + jt * 64 + r)) * QKV_LD
                              + h * DHEAD + (half_v ? 1024 : 512) + c * 8;
            cp16(dst + half_v * 8192 + r * 128 + SWZ128(r, c), src);
        }
        CP_COMMIT();
    };

    // ---- prologue: group0 = Q + KV0, group1 = KV1, group2 = KV2 ----
    #pragma unroll
    for (int i = 0; i < 4; i++) {
        int s = tid + i * 256, r = s >> 3, c = s & 7;
        cp16(smb + FL_Q + r * 128 + SWZ128(r, c),
             qkv + ((size_t)(b * NSEQ + i0 + r)) * QKV_LD + h * DHEAD + c * 8);
    }
    issue_kv(0, 0);
    issue_kv(1, 1);
    issue_kv(2, 2);

    float oacc[2][8][4];
    #pragma unroll
    for (int mt = 0; mt < 2; mt++)
        #pragma unroll
        for (int nt = 0; nt < 8; nt++)
            #pragma unroll
            for (int i = 0; i < 4; i++) oacc[mt][nt][i] = 0.0f;
    float l[4] = {0.f, 0.f, 0.f, 0.f};           // [mt*2 + rowhalf]

    const float* mrow = mask + ((size_t)h * NSEQ + (i0 + wrow + g)) * NSEQ;

    // ---- wait group 0 (Q + KV0); hoist ALL Q fragments (loop-invariant) ----
    CP_WAIT2();
    __syncthreads();
    uint32_t qf[4][2][4];
    #pragma unroll
    for (int ks = 0; ks < 4; ks++)
        #pragma unroll
        for (int mt = 0; mt < 2; mt++) {
            int r = wrow + mt * 16 + (lane & 15);
            int c = ks * 2 + (lane >> 4);
            LDSM_X4(qf[ks][mt][0], qf[ks][mt][1], qf[ks][mt][2], qf[ks][mt][3],
                    smb + FL_Q + r * 128 + SWZ128(r, c));
        }

    const float C = 0.125f * 1.4426950408889634f;    // scale * log2(e)

    for (int t = 0; t < 16; t++) {
        if (t > 0) {
            if (t <= 13)      { CP_WAIT2(); }
            else if (t == 14) { CP_WAIT1(); }
            else              { CP_WAIT0(); }
            __syncthreads();
        }
        if (t + 3 < 16) issue_kv((t + 3) & 3, t + 3);

        const uint32_t sK = smb + FL_KV + (t & 3) * FL_STAGE;
        const uint32_t sV = sK + 8192;

        #pragma unroll
        for (int ch = 0; ch < 2; ch++) {          // 16-j chunk within warp's half
            const int jl = jg * 32 + ch * 16;     // row within 64-j tile

            // ---- S chunk = Q @ K^T (32 rows x 16 j) ----
            float sacc[2][2][4];
            #pragma unroll
            for (int mt = 0; mt < 2; mt++)
                #pragma unroll
                for (int n2 = 0; n2 < 2; n2++)
                    #pragma unroll
                    for (int i = 0; i < 4; i++) sacc[mt][n2][i] = 0.0f;

            #pragma unroll
            for (int ks = 0; ks < 4; ks++) {
                uint32_t kb[4];
                int r = jl + (lane & 7) + ((lane >> 4) << 3);
                int c = ks * 2 + ((lane >> 3) & 1);
                LDSM_X4(kb[0], kb[1], kb[2], kb[3],
                        sK + r * 128 + SWZ128(r, c));
                #pragma unroll
                for (int mt = 0; mt < 2; mt++) {
                    mma_f16(sacc[mt][0], qf[ks][mt], &kb[0]);
                    mma_f16(sacc[mt][1], qf[ks][mt], &kb[2]);
                }
            }

            // ---- softmax (MUFU) + mask + pack to A-frags ----
            uint32_t pf[2][4];
            const int jc = t * 64 + jl + 2 * t4;
            #pragma unroll
            for (int mt = 0; mt < 2; mt++) {
                const float* mlo = mrow + (size_t)(mt * 16) * NSEQ;
                const float* mhi = mlo + (size_t)8 * NSEQ;
                #pragma unroll
                for (int n2 = 0; n2 < 2; n2++) {
                    float2 m0 = __ldg(reinterpret_cast<const float2*>(&mlo[jc + n2 * 8]));
                    float2 m1 = __ldg(reinterpret_cast<const float2*>(&mhi[jc + n2 * 8]));
                    float p0 = ex2a(sacc[mt][n2][0] * C);
                    float p1 = ex2a(sacc[mt][n2][1] * C);
                    float p2 = ex2a(sacc[mt][n2][2] * C);
                    float p3 = ex2a(sacc[mt][n2][3] * C);
                    l[mt * 2 + 0] += p0 + p1;
                    l[mt * 2 + 1] += p2 + p3;
                    pf[mt][n2 * 2 + 0] = pack2h(p0 * m0.x, p1 * m0.y);
                    pf[mt][n2 * 2 + 1] = pack2h(p2 * m1.x, p3 * m1.y);
                }
            }

            // ---- O += P-chunk @ V-chunk (d in 2 halves of 32) ----
            #pragma unroll
            for (int dh = 0; dh < 2; dh++) {
                uint32_t vb[4][2];
                #pragma unroll
                for (int m2 = 0; m2 < 2; m2++) {
                    int r = jl + (lane & 15);
                    int c = dh * 4 + m2 * 2 + (lane >> 4);
                    LDSM_X4_T(vb[m2*2][0], vb[m2*2][1], vb[m2*2+1][0], vb[m2*2+1][1],
                              sV + r * 128 + SWZ128(r, c));
                }
                #pragma unroll
                for (int mt = 0; mt < 2; mt++)
                    #pragma unroll
                    for (int n = 0; n < 4; n++)
                        mma_f16(oacc[mt][dh * 4 + n], pf[mt], vb[n]);
            }
        }
    }

    // ---- quad-lane reduce l (each lane ends with its row's partial sum) ----
    #pragma unroll
    for (int i = 0; i < 4; i++) {
        l[i] += __shfl_xor_sync(0xffffffffu, l[i], 1);
        l[i] += __shfl_xor_sync(0xffffffffu, l[i], 2);
    }

    // ---- cross-jg reduction via smem (reuse KV area; all cp.async drained) ----
    __syncthreads();
    float* osm  = reinterpret_cast<float*>(sm + FL_KV);          // [128][64] f32
    float* larr = reinterpret_cast<float*>(sm + FL_KV + 32768);  // [128]

    if (jg == 1) {
        #pragma unroll
        for (int mt = 0; mt < 2; mt++) {
            const int rlo = wrow + mt * 16 + g;
            #pragma unroll
            for (int nt = 0; nt < 8; nt++) {
                const int col = nt * 8 + 2 * t4;
                *reinterpret_cast<float2*>(&osm[rlo * 64 + col]) =
                    make_float2(oacc[mt][nt][0], oacc[mt][nt][1]);
                *reinterpret_cast<float2*>(&osm[(rlo + 8) * 64 + col]) =
                    make_float2(oacc[mt][nt][2], oacc[mt][nt][3]);
            }
            if (t4 == 0) {
                larr[rlo]     = l[mt * 2 + 0];
                larr[rlo + 8] = l[mt * 2 + 1];
            }
        }
    }
    __syncthreads();

    if (jg == 0) {
        #pragma unroll
        for (int mt = 0; mt < 2; mt++) {
            const int rlo = wrow + mt * 16 + g;
            const float inv0 = 1.0f / (l[mt * 2 + 0] + larr[rlo]);
            const float inv1 = 1.0f / (l[mt * 2 + 1] + larr[rlo + 8]);
            const size_t go = (size_t)(b * NSEQ + i0 + rlo) * DIM + h * DHEAD;
            #pragma unroll
            for (int nt = 0; nt < 8; nt++) {
                const int col = nt * 8 + 2 * t4;
                float2 s0 = *reinterpret_cast<float2*>(&osm[rlo * 64 + col]);
                float2 s1 = *reinterpret_cast<float2*>(&osm[(rlo + 8) * 64 + col]);
                *reinterpret_cast<uint32_t*>(&out[go + col]) =
                    pack2h((oacc[mt][nt][0] + s0.x) * inv0,
                           (oacc[mt][nt][1] + s0.y) * inv0);
                *reinterpret_cast<uint32_t*>(&out[go + 8 * DIM + col]) =
                    pack2h((oacc[mt][nt][2] + s1.x) * inv1,
                           (oacc[mt][nt][3] + s1.y) * inv1);
            }
        }
    }
}

// =====================================================================
// Host launch
// =====================================================================
extern "C" void kernel_launch(void* const* d_in, const int* in_sizes, int n_in,
                              void* d_out, int out_size)
{
    (void)in_sizes; (void)n_in; (void)out_size;
    const float* x    = (const float*)d_in[0];
    const float* Wqkv = (const float*)d_in[1];
    const float* Wout = (const float*)d_in[2];
    const float* bout = (const float*)d_in[3];
    const float* mask = (const float*)d_in[4];
    float* out = (float*)d_out;

    void *x16p, *qkvp, *aop, *wqp, *wop;
    cudaGetSymbolAddress(&x16p, g_x16);
    cudaGetSymbolAddress(&qkvp, g_qkv16);
    cudaGetSymbolAddress(&aop,  g_ao16);
    cudaGetSymbolAddress(&wqp,  g_wqkvT);
    cudaGetSymbolAddress(&wop,  g_woutT);
    __half* x16 = (__half*)x16p;
    __half* qkv = (__half*)qkvp;
    __half* ao  = (__half*)aop;
    __half* wqT = (__half*)wqp;
    __half* woT = (__half*)wop;

    const int M = BATCH * NSEQ;

    cudaFuncSetAttribute(hgemm<true>,
        cudaFuncAttributeMaxDynamicSharedMemorySize, HG_SMEM);
    cudaFuncSetAttribute(hgemm<false>,
        cudaFuncAttributeMaxDynamicSharedMemorySize, HG_SMEM);
    cudaFuncSetAttribute(hflash,
        cudaFuncAttributeMaxDynamicSharedMemorySize, FL_SMEM);

    // converts
    f32to16<<<(M * DIM / 4 + 255) / 256, 256>>>(x, x16, M * DIM / 4);
    transpose16<<<dim3(QKV_LD / 32, DIM / 32), dim3(32, 8)>>>(Wqkv, wqT, DIM, QKV_LD);
    transpose16<<<dim3(DIM / 32, DIM / 32), dim3(32, 8)>>>(Wout, woT, DIM, DIM);

    // GEMM1: qkv(fp16) = x @ W_qkv
    hgemm<true><<<dim3(QKV_LD / 128, M / 128), 256, HG_SMEM>>>(
        x16, wqT, qkv, DIM, QKV_LD, nullptr);

    // flash attention -> ao (fp16)
    hflash<<<dim3(NSEQ / 128, NHEAD, BATCH), 256, FL_SMEM>>>(qkv, mask, ao);

    // GEMM3: out(fp32) = ao @ W_out + b_out
    hgemm<false><<<dim3(DIM / 128, M / 128), 256, HG_SMEM>>>(
        ao, woT, out, DIM, DIM, bout);
}

// round 17
// speedup vs baseline: 1.3237x; 1.3237x over previous
#include <cuda_runtime.h>
#include <cuda_fp16.h>
#include <math.h>
#include <stdint.h>

// ---------------- problem constants ----------------
#define BATCH   32
#define NSEQ    1024
#define DIM     512
#define NHEAD   8
#define DHEAD   64
#define QKV_LD  1536

// ---------------- scratch (device globals) ----------------
__device__ __half g_x16  [(size_t)BATCH * NSEQ * DIM];     // x in fp16
__device__ __half g_qkv16[(size_t)BATCH * NSEQ * QKV_LD];  // qkv fp16
__device__ __half g_ao16 [(size_t)BATCH * NSEQ * DIM];     // attn out fp16
__device__ __half g_wqkvT[(size_t)QKV_LD * DIM];           // [N][K] fp16
__device__ __half g_woutT[(size_t)DIM * DIM];              // [N][K] fp16

// =====================================================================
// helpers
// =====================================================================
__device__ __forceinline__ uint32_t smem_u32(const void* p) {
    uint32_t a;
    asm("{ .reg .u64 t; cvta.to.shared.u64 t, %1; cvt.u32.u64 %0, t; }"
        : "=r"(a) : "l"(p));
    return a;
}

__device__ __forceinline__ uint32_t pack2h(float a, float b) {
    __half2 h = __floats2half2_rn(a, b);
    return *reinterpret_cast<uint32_t*>(&h);
}

// MUFU exp2 — 1 issue slot, ~2^-22 rel accuracy
__device__ __forceinline__ float ex2a(float x) {
    float r;
    asm("ex2.approx.f32 %0, %1;" : "=f"(r) : "f"(x));
    return r;
}

__device__ __forceinline__ void mma_f16(float* c, const uint32_t* a,
                                        const uint32_t* b) {
    asm volatile(
        "mma.sync.aligned.m16n8k16.row.col.f32.f16.f16.f32 "
        "{%0,%1,%2,%3}, {%4,%5,%6,%7}, {%8,%9}, {%0,%1,%2,%3};\n"
        : "+f"(c[0]), "+f"(c[1]), "+f"(c[2]), "+f"(c[3])
        : "r"(a[0]), "r"(a[1]), "r"(a[2]), "r"(a[3]),
          "r"(b[0]), "r"(b[1]));
}

#define LDSM_X4(r0, r1, r2, r3, addr)                                        \
    asm volatile("ldmatrix.sync.aligned.m8n8.x4.shared.b16 {%0,%1,%2,%3}, [%4];" \
        : "=r"(r0), "=r"(r1), "=r"(r2), "=r"(r3) : "r"(addr))

#define LDSM_X4_T(r0, r1, r2, r3, addr)                                      \
    asm volatile("ldmatrix.sync.aligned.m8n8.x4.trans.shared.b16 {%0,%1,%2,%3}, [%4];" \
        : "=r"(r0), "=r"(r1), "=r"(r2), "=r"(r3) : "r"(addr))

__device__ __forceinline__ void cp16(uint32_t dst, const void* src) {
    asm volatile("cp.async.cg.shared.global [%0], [%1], 16;"
                 :: "r"(dst), "l"(src));
}
#define CP_COMMIT() asm volatile("cp.async.commit_group;" ::: "memory")
#define CP_WAIT2()  asm volatile("cp.async.wait_group 2;" ::: "memory")
#define CP_WAIT1()  asm volatile("cp.async.wait_group 1;" ::: "memory")
#define CP_WAIT0()  asm volatile("cp.async.wait_group 0;" ::: "memory")

// 16B-chunk swizzle within 128B rows
#define SWZ128(r, c) (((c) * 16) ^ (((r) & 7) * 16))

// =====================================================================
// converters
// =====================================================================
__global__ __launch_bounds__(256) void f32to16(
    const float* __restrict__ in, __half* __restrict__ out, int n4)
{
    int i = blockIdx.x * blockDim.x + threadIdx.x;
    if (i < n4) {
        float4 v = reinterpret_cast<const float4*>(in)[i];
        uint2 u = {pack2h(v.x, v.y), pack2h(v.z, v.w)};
        reinterpret_cast<uint2*>(out)[i] = u;
    }
}

// out[n*K + k] = (half)in[k*N + n]
__global__ __launch_bounds__(256) void transpose16(
    const float* __restrict__ in, __half* __restrict__ out, int K, int N)
{
    __shared__ float t[32][33];
    int k0 = blockIdx.y * 32, n0 = blockIdx.x * 32;
    int x = threadIdx.x, y = threadIdx.y;        // 32 x 8
    #pragma unroll
    for (int i = 0; i < 32; i += 8)
        t[y + i][x] = in[(size_t)(k0 + y + i) * N + n0 + x];
    __syncthreads();
    #pragma unroll
    for (int i = 0; i < 32; i += 8)
        out[(size_t)(n0 + y + i) * K + k0 + x] = __float2half(t[x][y + i]);
}

// =====================================================================
// fp16 GEMM, cp.async 3-stage (unchanged — stable ~146us)
// =====================================================================
#define HG_STAGE 32768                         // A 16KB + B 16KB
#define HG_SMEM  (3 * HG_STAGE)

template <bool OUT_HALF>
__global__ __launch_bounds__(256, 2) void hgemm(
    const __half* __restrict__ A, const __half* __restrict__ Bt,
    void* __restrict__ Cv, int K, int Nglob, const float* __restrict__ bias)
{
    extern __shared__ __align__(16) char sm[];
    const uint32_t smb = smem_u32(sm);
    const int tid = threadIdx.x, lane = tid & 31, wid = tid >> 5;
    const int g = lane >> 2, t4 = lane & 3;
    const int wm = wid >> 2, wn = wid & 3;
    const int row0 = blockIdx.y * 128, col0 = blockIdx.x * 128;

    auto issue = [&](int st, int kt) {
        const uint32_t dA = smb + st * HG_STAGE;
        const uint32_t dB = dA + 16384;
        #pragma unroll
        for (int i = 0; i < 4; i++) {
            int s = tid + i * 256, r = s >> 3, c = s & 7;
            cp16(dA + r * 128 + SWZ128(r, c),
                 A + (size_t)(row0 + r) * K + kt * 64 + c * 8);
            cp16(dB + r * 128 + SWZ128(r, c),
                 Bt + (size_t)(col0 + r) * K + kt * 64 + c * 8);
        }
        CP_COMMIT();
    };

    float acc[4][4][4];
    #pragma unroll
    for (int mt = 0; mt < 4; mt++)
        #pragma unroll
        for (int nt = 0; nt < 4; nt++)
            #pragma unroll
            for (int i = 0; i < 4; i++) acc[mt][nt][i] = 0.0f;

    const int KT = K / 64;
    issue(0, 0);
    issue(1, 1);

    int st = 0, sti = 2;
    for (int t = 0; t < KT; t++) {
        if (t == KT - 1) { CP_WAIT0(); } else { CP_WAIT1(); }
        __syncthreads();
        if (t + 2 < KT) issue(sti, t + 2);

        const uint32_t sA = smb + st * HG_STAGE;
        const uint32_t sB = sA + 16384;

        #pragma unroll
        for (int ks = 0; ks < 4; ks++) {
            uint32_t af[4][4];
            #pragma unroll
            for (int mt = 0; mt < 4; mt++) {
                int r = wm * 64 + mt * 16 + (lane & 15);
                int c = ks * 2 + (lane >> 4);
                LDSM_X4(af[mt][0], af[mt][1], af[mt][2], af[mt][3],
                        sA + r * 128 + SWZ128(r, c));
            }
            uint32_t bf[4][2];
            #pragma unroll
            for (int np = 0; np < 2; np++) {
                int r = wn * 32 + np * 16 + (lane & 7) + ((lane >> 4) << 3);
                int c = ks * 2 + ((lane >> 3) & 1);
                LDSM_X4(bf[np*2][0], bf[np*2][1], bf[np*2+1][0], bf[np*2+1][1],
                        sB + r * 128 + SWZ128(r, c));
            }
            #pragma unroll
            for (int mt = 0; mt < 4; mt++)
                #pragma unroll
                for (int nt = 0; nt < 4; nt++)
                    mma_f16(acc[mt][nt], af[mt], bf[nt]);
        }

        if (++st == 3) st = 0;
        if (++sti == 3) sti = 0;
    }

    #pragma unroll
    for (int mt = 0; mt < 4; mt++) {
        const int r = row0 + wm * 64 + mt * 16 + g;
        #pragma unroll
        for (int nt = 0; nt < 4; nt++) {
            const int cc = col0 + wn * 32 + nt * 8 + t4 * 2;
            if (OUT_HALF) {
                __half* C = (__half*)Cv;
                *reinterpret_cast<uint32_t*>(&C[(size_t)r * Nglob + cc]) =
                    pack2h(acc[mt][nt][0], acc[mt][nt][1]);
                *reinterpret_cast<uint32_t*>(&C[(size_t)(r + 8) * Nglob + cc]) =
                    pack2h(acc[mt][nt][2], acc[mt][nt][3]);
            } else {
                float* C = (float*)Cv;
                float b0 = bias[cc], b1 = bias[cc + 1];
                *reinterpret_cast<float2*>(&C[(size_t)r * Nglob + cc]) =
                    make_float2(acc[mt][nt][0] + b0, acc[mt][nt][1] + b1);
                *reinterpret_cast<float2*>(&C[(size_t)(r + 8) * Nglob + cc]) =
                    make_float2(acc[mt][nt][2] + b0, acc[mt][nt][3] + b1);
            }
        }
    }
}

// =====================================================================
// flash attention v17 — crossbar fix with the register cap REMOVED.
// CTA: 128 q-rows, 128 threads (4 warps). Warp = 32 q-rows x ALL 64 j
// -> K/V fragment redundancy 8 -> 4, Q fully hoisted (zero steady Q
// crossbar), NO cross-warp epilogue exchange.
// __launch_bounds__(128, 2): 256-reg budget -> qf(32)+oacc(64) fit
// spill-free (the R16 failure was the 128-reg cap, not the retile).
// smem: Q 16KB | 4 stages x (K 8KB + V 8KB) = 80KB; 2 CTAs/SM = 160KB.
// =====================================================================
#define FL_Q     0
#define FL_KV    16384
#define FL_STAGE 16384
#define FL_SMEM  (16384 + 4 * FL_STAGE)

__global__ __launch_bounds__(128, 2) void hflash(
    const __half* __restrict__ qkv, const float* __restrict__ mask,
    __half* __restrict__ out)
{
    extern __shared__ __align__(16) char sm[];
    const uint32_t smb = smem_u32(sm);
    const int tid = threadIdx.x, lane = tid & 31, wid = tid >> 5;
    const int g = lane >> 2, t4 = lane & 3;
    const int b = blockIdx.z, h = blockIdx.y, i0 = blockIdx.x * 128;
    const int wrow = wid * 32;                    // warp's q-row base (4 warps)

    auto issue_kv = [&](int st, int jt) {
        const uint32_t dst = smb + FL_KV + st * FL_STAGE;
        #pragma unroll
        for (int i = 0; i < 8; i++) {
            int s = tid + i * 128;
            int half_v = (s >= 512);
            int r = (s & 511) >> 3, c = s & 7;
            const __half* src = qkv + ((size_t)(b * NSEQ + jt * 64 + r)) * QKV_LD
                              + h * DHEAD + (half_v ? 1024 : 512) + c * 8;
            cp16(dst + half_v * 8192 + r * 128 + SWZ128(r, c), src);
        }
        CP_COMMIT();
    };

    // ---- prologue: group0 = Q + KV0, group1 = KV1, group2 = KV2 ----
    #pragma unroll
    for (int i = 0; i < 8; i++) {
        int s = tid + i * 128, r = s >> 3, c = s & 7;
        cp16(smb + FL_Q + r * 128 + SWZ128(r, c),
             qkv + ((size_t)(b * NSEQ + i0 + r)) * QKV_LD + h * DHEAD + c * 8);
    }
    issue_kv(0, 0);
    issue_kv(1, 1);
    issue_kv(2, 2);

    float oacc[2][8][4];
    #pragma unroll
    for (int mt = 0; mt < 2; mt++)
        #pragma unroll
        for (int nt = 0; nt < 8; nt++)
            #pragma unroll
            for (int i = 0; i < 4; i++) oacc[mt][nt][i] = 0.0f;
    float l[4] = {0.f, 0.f, 0.f, 0.f};           // [mt*2 + rowhalf]

    const float* mrow = mask + ((size_t)h * NSEQ + (i0 + wrow + g)) * NSEQ;

    // ---- wait group 0 (Q + KV0); hoist ALL Q fragments (loop-invariant) ----
    CP_WAIT2();
    __syncthreads();
    uint32_t qf[4][2][4];
    #pragma unroll
    for (int ks = 0; ks < 4; ks++)
        #pragma unroll
        for (int mt = 0; mt < 2; mt++) {
            int r = wrow + mt * 16 + (lane & 15);
            int c = ks * 2 + (lane >> 4);
            LDSM_X4(qf[ks][mt][0], qf[ks][mt][1], qf[ks][mt][2], qf[ks][mt][3],
                    smb + FL_Q + r * 128 + SWZ128(r, c));
        }

    const float C = 0.125f * 1.4426950408889634f;    // scale * log2(e)

    for (int t = 0; t < 16; t++) {
        if (t > 0) {
            if (t <= 13)      { CP_WAIT2(); }
            else if (t == 14) { CP_WAIT1(); }
            else              { CP_WAIT0(); }
            __syncthreads();
        }
        if (t + 3 < 16) issue_kv((t + 3) & 3, t + 3);

        const uint32_t sK = smb + FL_KV + (t & 3) * FL_STAGE;
        const uint32_t sV = sK + 8192;

        #pragma unroll
        for (int ch = 0; ch < 4; ch++) {          // 16-j chunk (full 64 j/warp)
            const int jl = ch * 16;               // row within 64-j tile

            // ---- S chunk = Q @ K^T (32 rows x 16 j) ----
            float sacc[2][2][4];
            #pragma unroll
            for (int mt = 0; mt < 2; mt++)
                #pragma unroll
                for (int n2 = 0; n2 < 2; n2++)
                    #pragma unroll
                    for (int i = 0; i < 4; i++) sacc[mt][n2][i] = 0.0f;

            #pragma unroll
            for (int ks = 0; ks < 4; ks++) {
                uint32_t kb[4];
                int r = jl + (lane & 7) + ((lane >> 4) << 3);
                int c = ks * 2 + ((lane >> 3) & 1);
                LDSM_X4(kb[0], kb[1], kb[2], kb[3],
                        sK + r * 128 + SWZ128(r, c));
                #pragma unroll
                for (int mt = 0; mt < 2; mt++) {
                    mma_f16(sacc[mt][0], qf[ks][mt], &kb[0]);
                    mma_f16(sacc[mt][1], qf[ks][mt], &kb[2]);
                }
            }

            // ---- softmax (MUFU) + mask + pack to A-frags ----
            uint32_t pf[2][4];
            const int jc = t * 64 + jl + 2 * t4;
            #pragma unroll
            for (int mt = 0; mt < 2; mt++) {
                const float* mlo = mrow + (size_t)(mt * 16) * NSEQ;
                const float* mhi = mlo + (size_t)8 * NSEQ;
                #pragma unroll
                for (int n2 = 0; n2 < 2; n2++) {
                    float2 m0 = __ldg(reinterpret_cast<const float2*>(&mlo[jc + n2 * 8]));
                    float2 m1 = __ldg(reinterpret_cast<const float2*>(&mhi[jc + n2 * 8]));
                    float p0 = ex2a(sacc[mt][n2][0] * C);
                    float p1 = ex2a(sacc[mt][n2][1] * C);
                    float p2 = ex2a(sacc[mt][n2][2] * C);
                    float p3 = ex2a(sacc[mt][n2][3] * C);
                    l[mt * 2 + 0] += p0 + p1;
                    l[mt * 2 + 1] += p2 + p3;
                    pf[mt][n2 * 2 + 0] = pack2h(p0 * m0.x, p1 * m0.y);
                    pf[mt][n2 * 2 + 1] = pack2h(p2 * m1.x, p3 * m1.y);
                }
            }

            // ---- O += P-chunk @ V-chunk (d in 2 halves of 32) ----
            #pragma unroll
            for (int dh = 0; dh < 2; dh++) {
                uint32_t vb[4][2];
                #pragma unroll
                for (int m2 = 0; m2 < 2; m2++) {
                    int r = jl + (lane & 15);
                    int c = dh * 4 + m2 * 2 + (lane >> 4);
                    LDSM_X4_T(vb[m2*2][0], vb[m2*2][1], vb[m2*2+1][0], vb[m2*2+1][1],
                              sV + r * 128 + SWZ128(r, c));
                }
                #pragma unroll
                for (int mt = 0; mt < 2; mt++)
                    #pragma unroll
                    for (int n = 0; n < 4; n++)
                        mma_f16(oacc[mt][dh * 4 + n], pf[mt], vb[n]);
            }
        }
    }

    // ---- quad-lane reduce l, normalize, write (no cross-warp exchange) ----
    #pragma unroll
    for (int i = 0; i < 4; i++) {
        l[i] += __shfl_xor_sync(0xffffffffu, l[i], 1);
        l[i] += __shfl_xor_sync(0xffffffffu, l[i], 2);
    }

    #pragma unroll
    for (int mt = 0; mt < 2; mt++) {
        const float inv0 = 1.0f / l[mt * 2 + 0];
        const float inv1 = 1.0f / l[mt * 2 + 1];
        const size_t r0 = (size_t)(b * NSEQ + i0 + wrow + mt * 16 + g);
        #pragma unroll
        for (int nt = 0; nt < 8; nt++) {
            const int cc = h * DHEAD + nt * 8 + 2 * t4;
            *reinterpret_cast<uint32_t*>(&out[r0 * DIM + cc]) =
                pack2h(oacc[mt][nt][0] * inv0, oacc[mt][nt][1] * inv0);
            *reinterpret_cast<uint32_t*>(&out[(r0 + 8) * DIM + cc]) =
                pack2h(oacc[mt][nt][2] * inv1, oacc[mt][nt][3] * inv1);
        }
    }
}

// =====================================================================
// Host launch
// =====================================================================
extern "C" void kernel_launch(void* const* d_in, const int* in_sizes, int n_in,
                              void* d_out, int out_size)
{
    (void)in_sizes; (void)n_in; (void)out_size;
    const float* x    = (const float*)d_in[0];
    const float* Wqkv = (const float*)d_in[1];
    const float* Wout = (const float*)d_in[2];
    const float* bout = (const float*)d_in[3];
    const float* mask = (const float*)d_in[4];
    float* out = (float*)d_out;

    void *x16p, *qkvp, *aop, *wqp, *wop;
    cudaGetSymbolAddress(&x16p, g_x16);
    cudaGetSymbolAddress(&qkvp, g_qkv16);
    cudaGetSymbolAddress(&aop,  g_ao16);
    cudaGetSymbolAddress(&wqp,  g_wqkvT);
    cudaGetSymbolAddress(&wop,  g_woutT);
    __half* x16 = (__half*)x16p;
    __half* qkv = (__half*)qkvp;
    __half* ao  = (__half*)aop;
    __half* wqT = (__half*)wqp;
    __half* woT = (__half*)wop;

    const int M = BATCH * NSEQ;

    cudaFuncSetAttribute(hgemm<true>,
        cudaFuncAttributeMaxDynamicSharedMemorySize, HG_SMEM);
    cudaFuncSetAttribute(hgemm<false>,
        cudaFuncAttributeMaxDynamicSharedMemorySize, HG_SMEM);
    cudaFuncSetAttribute(hflash,
        cudaFuncAttributeMaxDynamicSharedMemorySize, FL_SMEM);

    // converts
    f32to16<<<(M * DIM / 4 + 255) / 256, 256>>>(x, x16, M * DIM / 4);
    transpose16<<<dim3(QKV_LD / 32, DIM / 32), dim3(32, 8)>>>(Wqkv, wqT, DIM, QKV_LD);
    transpose16<<<dim3(DIM / 32, DIM / 32), dim3(32, 8)>>>(Wout, woT, DIM, DIM);

    // GEMM1: qkv(fp16) = x @ W_qkv
    hgemm<true><<<dim3(QKV_LD / 128, M / 128), 256, HG_SMEM>>>(
        x16, wqT, qkv, DIM, QKV_LD, nullptr);

    // flash attention -> ao (fp16)
    hflash<<<dim3(NSEQ / 128, NHEAD, BATCH), 128, FL_SMEM>>>(qkv, mask, ao);

    // GEMM3: out(fp32) = ao @ W_out + b_out
    hgemm<false><<<dim3(DIM / 128, M / 128), 256, HG_SMEM>>>(
        ao, woT, out, DIM, DIM, bout);
}